// round 15
// baseline (speedup 1.0000x reference)
#include <cuda_runtime.h>
#include <cuda_fp16.h>
#include <cstdint>
#include <cstddef>

#define BSZ   8192
#define DIMN  100
#define NSTEP 49
#define WH    256
#define RRATE 0.05f
#define KP1   112

// ---------------- device scratch (static, no allocations) ----------------
__device__ float g_volpre[(size_t)NSTEP * BSZ * DIMN];
__device__ float g_Sbuf[2][BSZ * DIMN];
__device__ float g_C[(size_t)2 * BSZ * DIMN];          // fused out: grad rows | v rows
__device__ float g_vsave[BSZ];
__device__ float g_stoch[BSZ];
__device__ float g_err[BSZ];
__device__ float g_bvout[DIMN];
// pre-split weights ([n][k] K-major, hi/lo halves, zero-padded)
__device__ __align__(16) __half g_Win_h[2][WH * KP1],   g_Win_l[2][WH * KP1];
__device__ __align__(16) __half g_Wh_h[2][3 * WH * WH], g_Wh_l[2][3 * WH * WH];
__device__ __align__(16) __half g_Wfin_h[2][WH * WH],   g_Wfin_l[2][WH * WH];
__device__ __align__(16) __half g_V_h[DIMN * KP1],      g_V_l[DIMN * KP1];

// ---------------- helpers ----------------
__device__ __forceinline__ uint32_t smem_u32(const void* p) {
    uint32_t a;
    asm("{ .reg .u64 t; cvta.to.shared.u64 t, %1; cvt.u32.u64 %0, t; }" : "=r"(a) : "l"(p));
    return a;
}
__device__ __forceinline__ void split2(float x0, float x1, uint32_t& h, uint32_t& l) {
    __half2 hh = __floats2half2_rn(x0, x1);
    float2 hf = __half22float2(hh);
    __half2 ll = __floats2half2_rn(x0 - hf.x, x1 - hf.y);
    h = *reinterpret_cast<uint32_t*>(&hh);
    l = *reinterpret_cast<uint32_t*>(&ll);
}
__device__ __forceinline__ void mma16(float d[4], const uint32_t a[4],
                                      uint32_t b0, uint32_t b1) {
    asm volatile(
        "mma.sync.aligned.m16n8k16.row.col.f32.f16.f16.f32 "
        "{%0,%1,%2,%3}, {%4,%5,%6,%7}, {%8,%9}, {%0,%1,%2,%3};"
        : "+f"(d[0]), "+f"(d[1]), "+f"(d[2]), "+f"(d[3])
        : "r"(a[0]), "r"(a[1]), "r"(a[2]), "r"(a[3]), "r"(b0), "r"(b1));
}
__device__ __forceinline__ void ldm4(uint32_t r[4], uint32_t addr) {
    asm volatile("ldmatrix.sync.aligned.m8n8.x4.shared.b16 {%0,%1,%2,%3}, [%4];"
                 : "=r"(r[0]), "=r"(r[1]), "=r"(r[2]), "=r"(r[3]) : "r"(addr));
}

// ================= FUSED TRUNK =================
// smem: act (128 rows x 256 f32, stride 1040B) | A stage x2 | B stage x2
#define ACT_STRIDE 1040
#define ACT_BYTES  (128 * ACT_STRIDE)             // 133120
#define ASTG_OFF   ACT_BYTES
#define ASTG_BYTES 12288                           // hi 6144 + lo 6144 (128 rows x 48B)
#define BSTG_OFF   (ASTG_OFF + 2 * ASTG_BYTES)     // 157696
#define BSTG_BYTES 24576                           // hi 12288 + lo 12288 (256 rows x 48B)
#define FUSED_SMEM (BSTG_OFF + 2 * BSTG_BYTES)     // 206848

// 128 CTAs x 512 threads; CTA owns 128 rows of the 16384-row dual stack.
// Runs: L1 (K=112) + 3 hidden (K=256) + final gradv layer (K=256, N<=100 out).
__global__ __launch_bounds__(512, 1)
void fused_trunk(const float* __restrict__ S,
                 const float* __restrict__ bg_in, const float* __restrict__ bv_in,
                 const float* __restrict__ bg_h,  const float* __restrict__ bv_h,
                 const float* __restrict__ bg_out, const float* __restrict__ bvo,
                 const float* __restrict__ Wg_in_orig, const float* __restrict__ Wv_in_orig,
                 const float* __restrict__ tg, int tIdx,
                 float* __restrict__ Cout)
{
    extern __shared__ char smc[];
    const uint32_t smemBase = smem_u32(smc);

    const int tid    = threadIdx.x;
    const int lane   = tid & 31;
    const int wid    = tid >> 5;       // 0..15
    const int warp_m = wid & 3;        // 4 warps down M (32 rows each)
    const int warp_n = wid >> 2;       // 4 warps along N (64 cols each)
    const int mBase  = blockIdx.x * 128;
    const bool hiH   = (int)blockIdx.x >= 64;   // v-net half

    const int qrow = lane >> 2;
    const int qk   = lane & 3;

    // staging indices
    const int rA  = tid >> 2;          // 0..127 (A rows, 4 thr/row)
    const int c40 = (tid & 3) << 2;    // k float offset 0,4,8,12
    const int rB  = tid >> 1;          // 0..255 (B rows, 2 thr/row)
    const int sB  = tid & 1;           // k-group 0/1
    const int arS = (mBase + rA) & (BSZ - 1);   // wrapped S row for layer 1

    // ldmatrix offsets
    const int l15 = lane & 15;
    const int lc  = (lane >> 4) << 4;
    const uint32_t offA0 = (uint32_t)ASTG_OFF + (uint32_t)(warp_m * 32 + l15) * 48 + lc;
    const uint32_t offA1 = offA0 + 16 * 48;
    const uint32_t offB  = (uint32_t)BSTG_OFF + (uint32_t)(warp_n * 64 + l15) * 48 + lc;

    // per-layer weight/bias tables
    const int h = hiH ? 1 : 0;
    const __half* BhT[5] = { g_Win_h[h], g_Wh_h[h], g_Wh_h[h] + 65536,
                             g_Wh_h[h] + 2 * 65536, g_Wfin_h[h] };
    const __half* BlT[5] = { g_Win_l[h], g_Wh_l[h], g_Wh_l[h] + 65536,
                             g_Wh_l[h] + 2 * 65536, g_Wfin_l[h] };
    const float* biasT[5] = { hiH ? bv_in : bg_in,
                              hiH ? bv_h : bg_h,
                              (hiH ? bv_h : bg_h) + WH,
                              (hiH ? bv_h : bg_h) + 2 * WH,
                              hiH ? bvo : bg_out };
    const float* w0 = hiH ? Wv_in_orig : Wg_in_orig;   // t-row of input layer
    const float tval = __ldg(tg + tIdx);

#pragma unroll 1
    for (int l = 0; l < 5; ++l) {
        const __half* Bh = BhT[l];
        const __half* Bl = BlT[l];
        const int KP = (l == 0) ? KP1 : WH;
        const int nChunks = KP >> 4;

        float acc[2][8][4];
#pragma unroll
        for (int i = 0; i < 2; ++i)
#pragma unroll
            for (int j = 0; j < 8; ++j)
#pragma unroll
                for (int q = 0; q < 4; ++q) acc[i][j][q] = 0.f;

        float4 av;
        uint4 pbh, pbl;
        auto prefetch = [&](int kc) {
            const int gc = (kc << 4) + c40;
            if (l == 0) {
                av = make_float4(0.f, 0.f, 0.f, 0.f);
                if (gc < DIMN)
                    av = *(const float4*)(S + (size_t)arS * DIMN + gc);
            } else {
                av = *(const float4*)(smc + (size_t)rA * ACT_STRIDE + gc * 4);
            }
            const size_t ub = (size_t)rB * KP + (kc << 4) + (sB << 3);
            pbh = *(const uint4*)(Bh + ub);
            pbl = *(const uint4*)(Bl + ub);
        };
        auto store = [&](int b) {
            char* abuf = smc + ASTG_OFF + b * ASTG_BYTES;
            uint32_t h0, l0, h1, l1;
            split2(av.x, av.y, h0, l0); split2(av.z, av.w, h1, l1);
            const uint32_t ra = (uint32_t)rA * 48 + c40 * 2;
            *(uint2*)(abuf + ra)        = make_uint2(h0, h1);
            *(uint2*)(abuf + 6144 + ra) = make_uint2(l0, l1);
            char* bbuf = smc + BSTG_OFF + b * BSTG_BYTES;
            const uint32_t ro = (uint32_t)rB * 48 + sB * 16;
            *(uint4*)(bbuf + ro)         = pbh;
            *(uint4*)(bbuf + 12288 + ro) = pbl;
        };

        prefetch(0);
        store(0);

        for (int kc = 0; kc < nChunks; ++kc) {
            __syncthreads();
            const bool more = (kc + 1 < nChunks);
            if (more) prefetch(kc + 1);

            const uint32_t aBase = smemBase + (kc & 1) * ASTG_BYTES;
            const uint32_t bBase = smemBase + (kc & 1) * BSTG_BYTES;

            uint32_t ax0[4], ax1[4], bb[4][4];
            // pass 1: Ah * Bh (bh resident)
            ldm4(ax0, aBase + offA0);
            ldm4(ax1, aBase + offA1);
#pragma unroll
            for (int t = 0; t < 4; ++t) ldm4(bb[t], bBase + offB + t * (16 * 48));
#pragma unroll
            for (int t = 0; t < 4; ++t) {
                mma16(acc[0][2 * t],     ax0, bb[t][0], bb[t][2]);
                mma16(acc[1][2 * t],     ax1, bb[t][0], bb[t][2]);
                mma16(acc[0][2 * t + 1], ax0, bb[t][1], bb[t][3]);
                mma16(acc[1][2 * t + 1], ax1, bb[t][1], bb[t][3]);
            }
            // pass 2: Al * Bh
            {
                uint32_t al0[4], al1[4];
                ldm4(al0, aBase + offA0 + 6144);
                ldm4(al1, aBase + offA1 + 6144);
#pragma unroll
                for (int t = 0; t < 4; ++t) {
                    mma16(acc[0][2 * t],     al0, bb[t][0], bb[t][2]);
                    mma16(acc[1][2 * t],     al1, bb[t][0], bb[t][2]);
                    mma16(acc[0][2 * t + 1], al0, bb[t][1], bb[t][3]);
                    mma16(acc[1][2 * t + 1], al1, bb[t][1], bb[t][3]);
                }
            }
            // pass 3: Ah * Bl
#pragma unroll
            for (int t = 0; t < 4; ++t) ldm4(bb[t], bBase + offB + 12288 + t * (16 * 48));
#pragma unroll
            for (int t = 0; t < 4; ++t) {
                mma16(acc[0][2 * t],     ax0, bb[t][0], bb[t][2]);
                mma16(acc[1][2 * t],     ax1, bb[t][0], bb[t][2]);
                mma16(acc[0][2 * t + 1], ax0, bb[t][1], bb[t][3]);
                mma16(acc[1][2 * t + 1], ax1, bb[t][1], bb[t][3]);
            }

            if (more) store((kc + 1) & 1);
        }
        __syncthreads();   // mainloop done (all reads of act complete)

        // ---------------- layer epilogue ----------------
        const float* bias = biasT[l];
#pragma unroll
        for (int jn = 0; jn < 8; ++jn) {
            int c = warp_n * 64 + jn * 8 + 2 * qk;
            if (l == 4 && c >= DIMN) continue;
            float b0e = __ldg(bias + c);
            float b1e = __ldg(bias + c + 1);
            if (l == 0) {
                b0e += tval * __ldg(w0 + c);
                b1e += tval * __ldg(w0 + c + 1);
            }
#pragma unroll
            for (int im = 0; im < 2; ++im) {
                int r = warp_m * 32 + im * 16 + qrow;
                float o00 = acc[im][jn][0] + b0e, o01 = acc[im][jn][1] + b1e;
                float o10 = acc[im][jn][2] + b0e, o11 = acc[im][jn][3] + b1e;
                if (l < 4) {
                    o00 = fmaxf(o00, 0.f); o01 = fmaxf(o01, 0.f);
                    o10 = fmaxf(o10, 0.f); o11 = fmaxf(o11, 0.f);
                    *(float2*)(smc + (size_t)r * ACT_STRIDE + c * 4)
                        = make_float2(o00, o01);
                    *(float2*)(smc + (size_t)(r + 8) * ACT_STRIDE + c * 4)
                        = make_float2(o10, o11);
                } else {
                    *(float2*)(Cout + (size_t)(mBase + r) * DIMN + c)
                        = make_float2(o00, o01);
                    *(float2*)(Cout + (size_t)(mBase + r + 8) * DIMN + c)
                        = make_float2(o10, o11);
                }
            }
        }
        __syncthreads();   // act writes visible before next layer stages
    }
}

// ================= volpre GEMM (R14 packed-B version) =================
#define A_LO_OFF  6144
#define B_HI_OFF  12288
#define B_LO_OFF  18432
#define BUF_BYTES 24576
#define DYN_SMEM  (2 * BUF_BYTES)
__global__ __launch_bounds__(256, 2)
void gemm_vol(const float* __restrict__ A,
              const __half* __restrict__ Bh, const __half* __restrict__ Bl,
              float* __restrict__ C, int N, int K, int KP)
{
    extern __shared__ uint32_t smw[];
    char* smc2 = (char*)smw;
    const uint32_t smemBase = smem_u32(smw);
    const int tid = threadIdx.x;
    const int lane = tid & 31;
    const int wid = tid >> 5;
    const int warp_m = wid & 3, warp_n = wid >> 2;
    const int mBase = blockIdx.y * 128;
    const int nBase = blockIdx.x * 128;
    const int qrow = lane >> 2, qk = lane & 3;

    float acc[2][8][4];
#pragma unroll
    for (int i = 0; i < 2; ++i)
#pragma unroll
        for (int j = 0; j < 8; ++j)
#pragma unroll
            for (int q = 0; q < 4; ++q) acc[i][j][q] = 0.f;

    const int r0 = tid >> 2, r1 = r0 + 64;
    const int c40 = (tid & 3) << 2;
    const int rL = tid >> 1, s = tid & 1;
    const int gnL = nBase + rL;
    const int l15 = lane & 15, lc = (lane >> 4) << 4;
    const uint32_t offA0 = (uint32_t)(warp_m * 32 + l15) * 48 + lc;
    const uint32_t offA1 = offA0 + 16 * 48;
    const uint32_t offB  = (uint32_t)B_HI_OFF + (uint32_t)(warp_n * 64 + l15) * 48 + lc;
    const int nChunks = (K + 15) >> 4;

    float4 av0, av1;
    uint4 pbh, pbl;
    auto prefetch = [&](int kc) {
        const int gc = (kc << 4) + c40;
        av0 = av1 = make_float4(0.f, 0.f, 0.f, 0.f);
        if (gc < K) {
            av0 = *(const float4*)(A + (size_t)(mBase + r0) * K + gc);
            av1 = *(const float4*)(A + (size_t)(mBase + r1) * K + gc);
        }
        if (gnL < N) {
            const size_t ub = (size_t)gnL * KP + (kc << 4) + (s << 3);
            pbh = *(const uint4*)(Bh + ub);
            pbl = *(const uint4*)(Bl + ub);
        } else pbh = pbl = make_uint4(0, 0, 0, 0);
    };
    auto store = [&](int b) {
        char* buf = smc2 + b * BUF_BYTES;
        const uint32_t ro0 = (uint32_t)r0 * 48 + c40 * 2;
        const uint32_t ro1 = (uint32_t)r1 * 48 + c40 * 2;
        uint32_t h0, l0, h1, l1;
        split2(av0.x, av0.y, h0, l0); split2(av0.z, av0.w, h1, l1);
        *(uint2*)(buf + ro0) = make_uint2(h0, h1);
        *(uint2*)(buf + A_LO_OFF + ro0) = make_uint2(l0, l1);
        split2(av1.x, av1.y, h0, l0); split2(av1.z, av1.w, h1, l1);
        *(uint2*)(buf + ro1) = make_uint2(h0, h1);
        *(uint2*)(buf + A_LO_OFF + ro1) = make_uint2(l0, l1);
        const uint32_t ro = (uint32_t)rL * 48 + s * 16;
        *(uint4*)(buf + B_HI_OFF + ro) = pbh;
        *(uint4*)(buf + B_LO_OFF + ro) = pbl;
    };

    prefetch(0); store(0);
    for (int kc = 0; kc < nChunks; ++kc) {
        __syncthreads();
        const bool more = (kc + 1 < nChunks);
        if (more) prefetch(kc + 1);
        const uint32_t base = smemBase + (kc & 1) * BUF_BYTES;
        uint32_t ax0[4], ax1[4], bb[4][4];
        ldm4(ax0, base + offA0);
        ldm4(ax1, base + offA1);
#pragma unroll
        for (int t = 0; t < 4; ++t) ldm4(bb[t], base + offB + t * (16 * 48));
#pragma unroll
        for (int t = 0; t < 4; ++t) {
            mma16(acc[0][2 * t],     ax0, bb[t][0], bb[t][2]);
            mma16(acc[1][2 * t],     ax1, bb[t][0], bb[t][2]);
            mma16(acc[0][2 * t + 1], ax0, bb[t][1], bb[t][3]);
            mma16(acc[1][2 * t + 1], ax1, bb[t][1], bb[t][3]);
        }
        {
            uint32_t al0[4], al1[4];
            ldm4(al0, base + offA0 + A_LO_OFF);
            ldm4(al1, base + offA1 + A_LO_OFF);
#pragma unroll
            for (int t = 0; t < 4; ++t) {
                mma16(acc[0][2 * t],     al0, bb[t][0], bb[t][2]);
                mma16(acc[1][2 * t],     al1, bb[t][0], bb[t][2]);
                mma16(acc[0][2 * t + 1], al0, bb[t][1], bb[t][3]);
                mma16(acc[1][2 * t + 1], al1, bb[t][1], bb[t][3]);
            }
        }
#pragma unroll
        for (int t = 0; t < 4; ++t)
            ldm4(bb[t], base + offB + (B_LO_OFF - B_HI_OFF) + t * (16 * 48));
#pragma unroll
        for (int t = 0; t < 4; ++t) {
            mma16(acc[0][2 * t],     ax0, bb[t][0], bb[t][2]);
            mma16(acc[1][2 * t],     ax1, bb[t][0], bb[t][2]);
            mma16(acc[0][2 * t + 1], ax0, bb[t][1], bb[t][3]);
            mma16(acc[1][2 * t + 1], ax1, bb[t][1], bb[t][3]);
        }
        if (more) store((kc + 1) & 1);
    }
#pragma unroll
    for (int jn = 0; jn < 8; ++jn) {
        int c = nBase + warp_n * 64 + jn * 8 + 2 * qk;
        if (c >= N) continue;
#pragma unroll
        for (int im = 0; im < 2; ++im) {
            int r = mBase + warp_m * 32 + im * 16 + qrow;
            *(float2*)(C + (size_t)r * N + c)
                = make_float2(acc[im][jn][0], acc[im][jn][1]);
            *(float2*)(C + (size_t)(r + 8) * N + c)
                = make_float2(acc[im][jn][2], acc[im][jn][3]);
        }
    }
}

// ---------------- prepack kernels (split for ncu launch indexing) ----------
__device__ __forceinline__ void wsplit(__half* dh, __half* dl, int idx, float v) {
    __half hh = __float2half_rn(v);
    dh[idx] = hh;
    dl[idx] = __float2half_rn(v - __half2float(hh));
}
__global__ void prepack_in(const float* __restrict__ Wg_in, const float* __restrict__ Wv_in) {
    for (int j = blockIdx.x * blockDim.x + threadIdx.x; j < 2 * WH * KP1;
         j += gridDim.x * blockDim.x) {
        int hsel = j / (WH * KP1), r = j % (WH * KP1);
        int n = r / KP1, k = r % KP1;
        const float* W = hsel ? Wv_in : Wg_in;
        wsplit(g_Win_h[hsel], g_Win_l[hsel], r,
               (k < DIMN) ? W[(size_t)(k + 1) * WH + n] : 0.f);
    }
}
__global__ void prepack_hid(const float* __restrict__ Wg_h, const float* __restrict__ Wv_h) {
    for (int j = blockIdx.x * blockDim.x + threadIdx.x; j < 2 * 3 * WH * WH;
         j += gridDim.x * blockDim.x) {
        int hsel = j / (3 * WH * WH), r = j % (3 * WH * WH);
        int l = r / 65536, rr = r % 65536;
        int n = rr / WH, k = rr % WH;
        const float* W = hsel ? Wv_h : Wg_h;
        wsplit(g_Wh_h[hsel], g_Wh_l[hsel], r, W[(size_t)l * 65536 + (size_t)k * WH + n]);
    }
}
__global__ void prepack_fin(const float* __restrict__ Wg_out, const float* __restrict__ Wv_out,
                            const float* __restrict__ bv_out) {
    for (int j = blockIdx.x * blockDim.x + threadIdx.x; j < 2 * WH * WH + DIMN;
         j += gridDim.x * blockDim.x) {
        if (j < 2 * WH * WH) {
            int hsel = j / (WH * WH), r = j % (WH * WH);
            int n = r / WH, k = r % WH;
            float v;
            if (hsel == 0) v = (n < DIMN) ? Wg_out[(size_t)k * DIMN + n] : 0.f;
            else           v = (n == 0) ? Wv_out[k] : 0.f;
            wsplit(g_Wfin_h[hsel], g_Wfin_l[hsel], r, v);
        } else {
            int b = j - 2 * WH * WH;
            g_bvout[b] = (b == 0) ? bv_out[0] : 0.f;
        }
    }
}
__global__ void prepack_V(const float* __restrict__ Vm) {
    for (int j = blockIdx.x * blockDim.x + threadIdx.x; j < DIMN * KP1;
         j += gridDim.x * blockDim.x) {
        int n = j / KP1, k = j % KP1;
        wsplit(g_V_h, g_V_l, j, (k < DIMN) ? Vm[(size_t)n * DIMN + k] : 0.f);
    }
}

// ---------------- step (+ previous-step error, vsave) ----------------
__global__ __launch_bounds__(256) void step_err(
    const float* __restrict__ S_old, const float* __restrict__ vp,
    const float* __restrict__ grad, const float* __restrict__ Cv,
    const float* __restrict__ tg, int i,
    float* __restrict__ S_new, float* __restrict__ stoch,
    float* __restrict__ vsave, float* __restrict__ err)
{
    int warp = threadIdx.x >> 5, lane = threadIdx.x & 31;
    int b = blockIdx.x * 8 + warp;
    float h  = tg[i + 1] - tg[i];
    float sq = sqrtf(h);
    float rh = RRATE * h;
    if (lane == 0) {
        float vC = Cv[(size_t)b * DIMN];
        if (i > 0) {
            float hp = tg[i] - tg[i - 1];
            float e = vC - vsave[b] * (1.f + RRATE * hp) - stoch[b];
            err[b] += e * e;
        }
        vsave[b] = vC;
    }
    const float* Sr = S_old + (size_t)b * DIMN;
    const float* vr = vp   + (size_t)b * DIMN;
    const float* gr = grad + (size_t)b * DIMN;
    float acc = 0.f;
    for (int d = lane; d < DIMN; d += 32) {
        float s   = Sr[d];
        float vol = s * (vr[d] * sq);
        acc += gr[d] * vol;
        S_new[(size_t)b * DIMN + d] = s + rh * s + vol;
    }
#pragma unroll
    for (int o = 16; o; o >>= 1) acc += __shfl_xor_sync(0xffffffffu, acc, o);
    if (lane == 0) stoch[b] = acc;
}

// ---------------- output packing + final error term ----------------
__global__ void pack_kernel(const float* __restrict__ Cv, const float* __restrict__ S,
                            const float* __restrict__ vsave, const float* __restrict__ stoch,
                            const float* __restrict__ tg, const float* __restrict__ err,
                            float* __restrict__ out)
{
    int i = blockIdx.x * 256 + threadIdx.x;
    if (i < BSZ * DIMN) out[BSZ + i] = S[i];
    if (i < BSZ) {
        float vC = Cv[(size_t)i * DIMN];
        float hp = tg[NSTEP] - tg[NSTEP - 1];
        float e = vC - vsave[i] * (1.f + RRATE * hp) - stoch[i];
        out[i] = vC;
        out[BSZ + BSZ * DIMN + i] = err[i] + e * e;
    }
}

extern "C" void kernel_launch(void* const* d_in, const int* in_sizes, int n_in,
                              void* d_out, int out_size)
{
    const float* S0     = (const float*)d_in[0];
    const float* dW     = (const float*)d_in[1];
    const float* tg     = (const float*)d_in[2];
    const float* Vm     = (const float*)d_in[3];
    const float* Wg_in  = (const float*)d_in[4];
    const float* bg_in  = (const float*)d_in[5];
    const float* Wg_h   = (const float*)d_in[6];
    const float* bg_h   = (const float*)d_in[7];
    const float* Wg_out = (const float*)d_in[8];
    const float* bg_out = (const float*)d_in[9];
    const float* Wv_in  = (const float*)d_in[10];
    const float* bv_in  = (const float*)d_in[11];
    const float* Wv_h   = (const float*)d_in[12];
    const float* bv_h   = (const float*)d_in[13];
    const float* Wv_out = (const float*)d_in[14];
    const float* bv_out = (const float*)d_in[15];

    cudaFuncSetAttribute(fused_trunk, cudaFuncAttributeMaxDynamicSharedMemorySize,
                         FUSED_SMEM);

    float *volpre, *Sb, *Cbuf, *vsave, *stoch, *err, *bvout;
    __half *V_h, *V_l;
    cudaGetSymbolAddress((void**)&volpre, g_volpre);
    cudaGetSymbolAddress((void**)&Sb,     g_Sbuf);
    cudaGetSymbolAddress((void**)&Cbuf,   g_C);
    cudaGetSymbolAddress((void**)&vsave,  g_vsave);
    cudaGetSymbolAddress((void**)&stoch,  g_stoch);
    cudaGetSymbolAddress((void**)&err,    g_err);
    cudaGetSymbolAddress((void**)&bvout,  g_bvout);
    cudaGetSymbolAddress((void**)&V_h,    g_V_h);
    cudaGetSymbolAddress((void**)&V_l,    g_V_l);

    float* Sbuf0 = Sb;
    float* Sbuf1 = Sb + (size_t)BSZ * DIMN;
    float* Cv = Cbuf + (size_t)BSZ * DIMN;

    // launches 0-3: prepack (4 small launches so launch #5 = first fused trunk)
    prepack_in <<<64, 256>>>(Wg_in, Wv_in);
    prepack_hid<<<512, 256>>>(Wg_h, Wv_h);
    prepack_fin<<<128, 256>>>(Wg_out, Wv_out, bv_out);
    prepack_V  <<<16, 256>>>(Vm);

    // launch 4: volpre = dW @ V^T
    {
        dim3 grid(1, (NSTEP * BSZ) / 128);
        gemm_vol<<<grid, 256, DYN_SMEM>>>(dW, V_h, V_l, volpre, DIMN, DIMN, KP1);
    }

    // launch 5: fused trunk on [t0, S0] -> grad_0, v_0
    fused_trunk<<<128, 512, FUSED_SMEM>>>(S0, bg_in, bv_in, bg_h, bv_h,
                                          bg_out, bvout, Wg_in, Wv_in,
                                          tg, 0, Cbuf);
    cudaMemsetAsync(err, 0, BSZ * sizeof(float));

    const float* Scur = S0;
    int sflip = 0;
    for (int i = 0; i < NSTEP; ++i) {
        float* Snew = sflip ? Sbuf1 : Sbuf0;
        step_err<<<BSZ / 8, 256>>>(Scur, volpre + (size_t)i * BSZ * DIMN,
                                   Cbuf, Cv, tg, i, Snew, stoch, vsave, err);
        fused_trunk<<<128, 512, FUSED_SMEM>>>(Snew, bg_in, bv_in, bg_h, bv_h,
                                              bg_out, bvout, Wg_in, Wv_in,
                                              tg, i + 1, Cbuf);
        Scur = Snew; sflip ^= 1;
    }

    pack_kernel<<<(BSZ * DIMN) / 256, 256>>>(Cv, Scur, vsave, stoch, tg, err,
                                             (float*)d_out);
}